// round 10
// baseline (speedup 1.0000x reference)
#include <cuda_runtime.h>
#include <math.h>

#define NN 50000
#define NE 400000
#define NG 64
#define DIN 200
#define DH 32
#define NBLK 196    // ceil(NN/256)
#define EBLK2 782   // ceil(NE/512)  (hist: 256 thr x 2 edges)
#define GBLK 391    // ceil(NN/128)  (GEMM blocks: 128 thr, 128 nodes, 64 cols)
#define SCB 1563    // ceil(NE/256)  (scatter blocks: 128 thr x 2 edges)
#define FBLK 1563   // ceil(NN/32)   (flayer blocks: 8 warps x 4 nodes)

// ---------------- scratch (device globals — no allocation allowed) ----------
// NOTE: never pass these as kernel args from host code (host shadow symbol +
// ATS silently reads zeros). Select ping-pong buffers with an int in device code.
__device__ __align__(16) float g_tr_a[NN * DH];
__device__ __align__(16) float g_tr_b[NN * DH];
__device__ __align__(16) float g_root_a[NN * DH];
__device__ __align__(16) float g_root_b[NN * DH];
__device__ float g_sums[NG * DH];

__device__ int g_flag_ei;    // nonzero -> edge_index is int32
__device__ int g_flag_b;     // nonzero -> batch is int32

__device__ int g_cnt[NN];
__device__ int g_off[NN];
__device__ int g_cur[NN];
__device__ int g_total;
__device__ int g_esrc[NE];
__device__ int g_gstart[NG + 1];

__device__ __forceinline__ float elu1(float v) { return v > 0.f ? v : expm1f(v); }

#define FMA_X2(acc, a, b) \
    asm("fma.rn.f32x2 %0, %1, %2, %0;" : "+l"(acc) : "l"(a), "l"(b))
#define DUP_X2(out, x) \
    asm("mov.b64 %0, {%1, %1};" : "=l"(out) : "r"(__float_as_uint(x)))
#define UNPK_X2(lo, hi, in) \
    asm("mov.b64 {%0, %1}, %2;" : "=f"(lo), "=f"(hi) : "l"(in))
#define PACK_X2(out, lo, hi) \
    asm("mov.b64 %0, {%1, %2};" : "=l"(out) : "f"(lo), "f"(hi))

// ---------------------------------------------------------------------------
// decode helpers (dtype-aware, clamped)
// ---------------------------------------------------------------------------
__device__ __forceinline__ int edge_at(const void* ei_raw, int idx, int is32)
{
    int v = is32 ? ((const int*)ei_raw)[idx] : (int)((const long long*)ei_raw)[idx];
    v &= 0x7fffffff;
    return (v < NN) ? v : 0;
}

__device__ __forceinline__ int batch_at(const void* b_raw, int i, int is32)
{
    int g = is32 ? ((const int*)b_raw)[i] : (int)((const long long*)b_raw)[i];
    g &= 0x7fffffff;
    return (g < NG) ? g : (NG - 1);
}

// ---------------------------------------------------------------------------
// Kernel 1: zero scratch + dtype detection (sample odd 32-bit words: int64
// values < 2^31 have zero high words; int32 payloads essentially never do)
// ---------------------------------------------------------------------------
__global__ void k_detect_zero(const unsigned* __restrict__ ei_w,
                              const unsigned* __restrict__ b_w)
{
    const int i = blockIdx.x * blockDim.x + threadIdx.x;
    if (i < NN) g_cnt[i] = 0;
    if (i < NG * DH) g_sums[i] = 0.f;
    if (i == 0) g_total = 0;

    if (blockIdx.x == 0) {
        __shared__ int s_ei, s_b;
        const int tid = threadIdx.x;
        if (tid == 0) { s_ei = 0; s_b = 0; }
        __syncthreads();
        { const int k = tid * 1562;  if (ei_w[2 * k + 1] != 0) atomicOr(&s_ei, 1); }
        { const int k = 24744 + tid; if (b_w[2 * k + 1] != 0)  atomicOr(&s_b, 1); }
        __syncthreads();
        if (tid == 0) { g_flag_ei = s_ei; g_flag_b = s_b; }
    }
}

// ---------------------------------------------------------------------------
// Kernel 2: dst histogram (decodes only dst half of raw edge_index)
// ---------------------------------------------------------------------------
__global__ void k_hist(const void* __restrict__ ei_raw)
{
    const int tid = blockIdx.x * 256 + threadIdx.x;
    const int is32 = g_flag_ei;
#pragma unroll
    for (int q = 0; q < 2; q++) {
        const int e = tid + q * (EBLK2 * 256);
        if (e < NE) atomicAdd(&g_cnt[edge_at(ei_raw, NE + e, is32)], 1);
    }
}

// ---------------------------------------------------------------------------
// Kernel 3: single-pass scan (block scan + atomic base; bases need not be
// monotone since consumers use beg + cnt) fused with graph-boundary build.
// ---------------------------------------------------------------------------
__global__ void k_scan_bounds(const void* __restrict__ b_raw)
{
    __shared__ int s[256];
    __shared__ int base_sh;
    const int tid = threadIdx.x;
    const int i = blockIdx.x * 256 + tid;
    const int v = (i < NN) ? g_cnt[i] : 0;
    s[tid] = v;
    __syncthreads();
#pragma unroll
    for (int d = 1; d < 256; d <<= 1) {
        const int t = (tid >= d) ? s[tid - d] : 0;
        __syncthreads();
        s[tid] += t;
        __syncthreads();
    }
    if (tid == 255) base_sh = atomicAdd(&g_total, s[255]);
    __syncthreads();
    if (i < NN) {
        const int o = base_sh + s[tid] - v;
        g_off[i] = o;
        g_cur[i] = o;
    }

    if (i < NN) {
        const int is32 = g_flag_b;
        const int g  = batch_at(b_raw, i, is32);
        const int gp = (i == 0) ? -1 : batch_at(b_raw, i - 1, is32);
        for (int q = gp + 1; q <= g; q++) g_gstart[q] = i;
        if (i == NN - 1)
            for (int q = g + 1; q <= NG; q++) g_gstart[q] = NN;
    }
}

// ---------------------------------------------------------------------------
// Kernel 4 (fused): blocks [0,GBLK) = GEMM1 (round-8 proven 8x8 tile);
// blocks [GBLK,GBLK+SCB) = CSR scatter (decodes raw edges directly).
// GEMM1: [50000,200] @ [W1r|W1l][200,64], packed f32x2, double-buffered smem,
// 128 threads / 128 nodes / 64 cols, one __syncthreads per K-tile.
// ---------------------------------------------------------------------------
__global__ __launch_bounds__(128) void k_gemm1_scatter(const float* __restrict__ x,
                                                       const float* __restrict__ Wr,
                                                       const float* __restrict__ Wl,
                                                       const float* __restrict__ b,
                                                       const void* __restrict__ ei_raw)
{
    if (blockIdx.x >= GBLK) {
        const int base = (blockIdx.x - GBLK) * 256 + threadIdx.x;
        const int is32 = g_flag_ei;
#pragma unroll
        for (int q = 0; q < 2; q++) {
            const int e = base + q * 128;
            if (e < NE) {
                const int d = edge_at(ei_raw, NE + e, is32);
                const int s = edge_at(ei_raw, e, is32);
                const int pos = atomicAdd(&g_cur[d], 1);
                g_esrc[pos] = s;
            }
        }
        return;
    }

    __shared__ __align__(16) float Xs[2][8 * 128];   // [buf][k][node]
    __shared__ __align__(16) float Wsc[2][8 * 64];   // [buf][k*64+c]
    __shared__ float bs[32];

    const int tid = threadIdx.x;
    const int n0  = blockIdx.x * 128;
    if (tid < 32) bs[tid] = b[tid];

    const int cg = tid & 7;        // col group (8 cols = 4 packed pairs)
    const int ng = tid >> 3;       // node group (8 nodes), 0..15

    unsigned long long acc2[8][4];
#pragma unroll
    for (int i = 0; i < 8; i++)
#pragma unroll
        for (int j = 0; j < 4; j++) acc2[i][j] = 0ULL;

    const int  nld = n0 + tid;
    const bool vld = nld < NN;
    const float4* xrow = reinterpret_cast<const float4*>(x + (long)nld * DIN);

    float4 xa, xb;
    float  wv[4];

#define LOAD_TILE(t)                                                          \
    do {                                                                      \
        xa = make_float4(0.f, 0.f, 0.f, 0.f); xb = xa;                        \
        if (vld) { xa = xrow[(t) * 2]; xb = xrow[(t) * 2 + 1]; }              \
        _Pragma("unroll")                                                     \
        for (int j = 0; j < 4; j++) {                                         \
            const int idx = j * 128 + tid;       /* 0..511 = k*64+c */        \
            const int kk = idx >> 6, c = idx & 63;                            \
            wv[j] = (c < 32) ? Wr[((t) * 8 + kk) * 32 + c]                    \
                             : Wl[((t) * 8 + kk) * 32 + c - 32];              \
        }                                                                     \
    } while (0)

#define STORE_TILE(bf)                                                        \
    do {                                                                      \
        Xs[bf][0 * 128 + tid] = xa.x; Xs[bf][1 * 128 + tid] = xa.y;           \
        Xs[bf][2 * 128 + tid] = xa.z; Xs[bf][3 * 128 + tid] = xa.w;           \
        Xs[bf][4 * 128 + tid] = xb.x; Xs[bf][5 * 128 + tid] = xb.y;           \
        Xs[bf][6 * 128 + tid] = xb.z; Xs[bf][7 * 128 + tid] = xb.w;           \
        _Pragma("unroll")                                                     \
        for (int j = 0; j < 4; j++) Wsc[bf][j * 128 + tid] = wv[j];           \
    } while (0)

    LOAD_TILE(0);
    STORE_TILE(0);
    __syncthreads();

    int buf = 0;
    for (int t = 0; t < 25; t++) {
        if (t < 24) LOAD_TILE(t + 1);                // LDG in flight during compute

#pragma unroll
        for (int kk = 0; kk < 8; kk++) {
            const float4* xp = reinterpret_cast<const float4*>(Xs[buf] + kk * 128 + ng * 8);
            const float4 a0 = xp[0], a1 = xp[1];
            const unsigned long long* wp =
                reinterpret_cast<const unsigned long long*>(Wsc[buf] + kk * 64 + cg * 8);
            const unsigned long long w0 = wp[0], w1p = wp[1], w2p = wp[2], w3p = wp[3];
            const float xv[8] = {a0.x, a0.y, a0.z, a0.w, a1.x, a1.y, a1.z, a1.w};
#pragma unroll
            for (int i = 0; i < 8; i++) {
                unsigned long long xd;
                DUP_X2(xd, xv[i]);
                FMA_X2(acc2[i][0], xd, w0);
                FMA_X2(acc2[i][1], xd, w1p);
                FMA_X2(acc2[i][2], xd, w2p);
                FMA_X2(acc2[i][3], xd, w3p);
            }
        }

        if (t < 24) STORE_TILE(buf ^ 1);             // other buffer: race-free
        __syncthreads();
        buf ^= 1;
    }
#undef LOAD_TILE
#undef STORE_TILE

    const int c0 = cg * 8;
#pragma unroll
    for (int i = 0; i < 8; i++) {
        const int node = n0 + ng * 8 + i;
        if (node >= NN) continue;
        float c[8];
#pragma unroll
        for (int j = 0; j < 4; j++) UNPK_X2(c[2 * j], c[2 * j + 1], acc2[i][j]);
        float4 lo = make_float4(c[0], c[1], c[2], c[3]);
        float4 hi = make_float4(c[4], c[5], c[6], c[7]);
        if (cg < 4) {
            *reinterpret_cast<float4*>(g_tr_a + node * DH + c0)     = lo;
            *reinterpret_cast<float4*>(g_tr_a + node * DH + c0 + 4) = hi;
        } else {
            const int cc = c0 - 32;
            lo.x += bs[cc + 0]; lo.y += bs[cc + 1]; lo.z += bs[cc + 2]; lo.w += bs[cc + 3];
            hi.x += bs[cc + 4]; hi.y += bs[cc + 5]; hi.z += bs[cc + 6]; hi.w += bs[cc + 7];
            *reinterpret_cast<float4*>(g_root_a + node * DH + cc)     = lo;
            *reinterpret_cast<float4*>(g_root_a + node * DH + cc + 4) = hi;
        }
    }
}

// ---------------------------------------------------------------------------
// Fused layer kernel (layers 1->2, 2->3): warp per 4 nodes; vectorized gather
// (4 edges/iter, one float4 LDG per lane), W held in 32 packed registers.
// Buffers picked by sel in device code (sel=0: a->b, sel=1: b->a).
// ---------------------------------------------------------------------------
__global__ __launch_bounds__(256) void k_flayer(int sel,
                                                const float* __restrict__ Wr,
                                                const float* __restrict__ Wl,
                                                const float* __restrict__ b)
{
    __shared__ float hs[8][32];

    const int tid  = threadIdx.x;
    const int w    = tid >> 5;
    const int lane = tid & 31;

    // W into registers: lane holds (Wr[k][lane], Wl[k][lane]) for all 32 k
    unsigned long long Wreg[32];
#pragma unroll
    for (int kk = 0; kk < 32; kk++)
        PACK_X2(Wreg[kk], Wr[kk * 32 + lane], Wl[kk * 32 + lane]);
    const float bsv = b[lane];

    const float* tr_in   = sel ? g_tr_b   : g_tr_a;
    const float* root_in = sel ? g_root_b : g_root_a;
    float* tr_out   = sel ? g_tr_a   : g_tr_b;
    float* root_out = sel ? g_root_a : g_root_b;

    const int qe = lane >> 3;      // edge slot 0..3
    const int qc = lane & 7;       // col group (float4)

#pragma unroll
    for (int j = 0; j < 4; j++) {
        const int node = (blockIdx.x << 5) + (w << 2) + j;
        if (node >= NN) break;                        // warp-uniform

        const int beg = g_off[node];
        const int end = beg + g_cnt[node];
        float4 va = make_float4(0.f, 0.f, 0.f, 0.f);
        for (int k = beg + qe; k < end; k += 4) {     // 4 edges per warp-iter
            const int s = g_esrc[k];
            const float4 v = *reinterpret_cast<const float4*>(tr_in + s * DH + qc * 4);
            va.x += v.x; va.y += v.y; va.z += v.z; va.w += v.w;
        }
        // reduce across the 4 edge slots (lane bits 3,4)
        va.x += __shfl_xor_sync(0xffffffffu, va.x, 8);
        va.y += __shfl_xor_sync(0xffffffffu, va.y, 8);
        va.z += __shfl_xor_sync(0xffffffffu, va.z, 8);
        va.w += __shfl_xor_sync(0xffffffffu, va.w, 8);
        va.x += __shfl_xor_sync(0xffffffffu, va.x, 16);
        va.y += __shfl_xor_sync(0xffffffffu, va.y, 16);
        va.z += __shfl_xor_sync(0xffffffffu, va.z, 16);
        va.w += __shfl_xor_sync(0xffffffffu, va.w, 16);

        if (lane < 8) *reinterpret_cast<float4*>(&hs[w][lane * 4]) = va;
        __syncwarp();
        const float h = elu1(hs[w][lane] + root_in[node * DH + lane]);
        __syncwarp();
        hs[w][lane] = h;
        __syncwarp();

        unsigned long long a2 = 0ULL;
#pragma unroll
        for (int kk = 0; kk < 32; kk++) {
            unsigned long long hd;
            DUP_X2(hd, hs[w][kk]);                    // LDS broadcast
            FMA_X2(a2, hd, Wreg[kk]);
        }
        float m, r;
        UNPK_X2(m, r, a2);
        tr_out[node * DH + lane]   = m;
        root_out[node * DH + lane] = r + bsv;
        __syncwarp();
    }
}

// ---------------------------------------------------------------------------
// Fused layer 3 + pool: same vectorized gather; h = elu(aggr + root);
// atomicAdd into per-graph sums.
// ---------------------------------------------------------------------------
__global__ __launch_bounds__(256) void k_flayer3_pool(const void* __restrict__ b_raw)
{
    __shared__ float hs[8][32];

    const int tid  = threadIdx.x;
    const int w    = tid >> 5;
    const int lane = tid & 31;
    const int qe = lane >> 3;
    const int qc = lane & 7;
    const int is32b = g_flag_b;

#pragma unroll
    for (int j = 0; j < 4; j++) {
        const int node = (blockIdx.x << 5) + (w << 2) + j;
        if (node >= NN) break;                        // warp-uniform

        const int beg = g_off[node];
        const int end = beg + g_cnt[node];
        float4 va = make_float4(0.f, 0.f, 0.f, 0.f);
        for (int k = beg + qe; k < end; k += 4) {
            const int s = g_esrc[k];
            const float4 v = *reinterpret_cast<const float4*>(g_tr_a + s * DH + qc * 4);
            va.x += v.x; va.y += v.y; va.z += v.z; va.w += v.w;
        }
        va.x += __shfl_xor_sync(0xffffffffu, va.x, 8);
        va.y += __shfl_xor_sync(0xffffffffu, va.y, 8);
        va.z += __shfl_xor_sync(0xffffffffu, va.z, 8);
        va.w += __shfl_xor_sync(0xffffffffu, va.w, 8);
        va.x += __shfl_xor_sync(0xffffffffu, va.x, 16);
        va.y += __shfl_xor_sync(0xffffffffu, va.y, 16);
        va.z += __shfl_xor_sync(0xffffffffu, va.z, 16);
        va.w += __shfl_xor_sync(0xffffffffu, va.w, 16);

        if (lane < 8) *reinterpret_cast<float4*>(&hs[w][lane * 4]) = va;
        __syncwarp();
        const float h = elu1(hs[w][lane] + g_root_a[node * DH + lane]);
        __syncwarp();

        const int g = batch_at(b_raw, node, is32b);
        atomicAdd(&g_sums[g * DH + lane], h);
    }
}

// ---------------------------------------------------------------------------
// Head: pooled mean -> linear[32,2] -> log_softmax
// ---------------------------------------------------------------------------
__global__ void k_head(const float* __restrict__ Wlin, const float* __restrict__ blin,
                       float* __restrict__ out)
{
    const int gph = threadIdx.x;
    if (gph >= NG) return;
    const int cnt = g_gstart[gph + 1] - g_gstart[gph];
    const float inv = 1.f / fmaxf((float)cnt, 1.f);
    float l0 = blin[0], l1 = blin[1];
#pragma unroll
    for (int c = 0; c < DH; c++) {
        const float p = g_sums[gph * DH + c] * inv;
        l0 += p * Wlin[c * 2 + 0];
        l1 += p * Wlin[c * 2 + 1];
    }
    const float m   = fmaxf(l0, l1);
    const float lse = m + logf(expf(l0 - m) + expf(l1 - m));
    out[gph * 2 + 0] = l0 - lse;
    out[gph * 2 + 1] = l1 - lse;
}

// ---------------------------------------------------------------------------
extern "C" void kernel_launch(void* const* d_in, const int* in_sizes, int n_in,
                              void* d_out, int out_size)
{
    const void *p_x = 0, *p_ei = 0, *p_batch = 0;
    const void *p_W1[2] = {0, 0};
    const void *p_W23[4] = {0, 0, 0, 0};
    const void *p_b[3] = {0, 0, 0};
    const void *p_Wlin = 0, *p_blin = 0;
    int n64 = 0, n1024 = 0, n32 = 0;
    for (int i = 0; i < n_in; i++) {
        const int s = in_sizes[i];
        if      (s == NN * DIN) p_x = d_in[i];
        else if (s == 2 * NE)   p_ei = d_in[i];
        else if (s == NN)       p_batch = d_in[i];
        else if (s == DIN * DH) { if (n64 < 2) p_W1[n64++] = d_in[i]; }
        else if (s == DH * DH)  { if (n1024 < 4) p_W23[n1024++] = d_in[i]; }
        else if (s == DH)       { if (n32 < 3) p_b[n32++] = d_in[i]; }
        else if (s == DH * 2)   p_Wlin = d_in[i];
        else if (s == 2)        p_blin = d_in[i];
    }
    const float* x    = (const float*)p_x;
    const float* W1r  = (const float*)p_W1[0];
    const float* W1l  = (const float*)p_W1[1];
    const float* b1   = (const float*)p_b[0];
    const float* W2r  = (const float*)p_W23[0];
    const float* W2l  = (const float*)p_W23[1];
    const float* b2   = (const float*)p_b[1];
    const float* W3r  = (const float*)p_W23[2];
    const float* W3l  = (const float*)p_W23[3];
    const float* b3   = (const float*)p_b[2];
    const float* Wlin = (const float*)p_Wlin;
    const float* blin = (const float*)p_blin;
    float* out = (float*)d_out;

    k_detect_zero<<<NBLK, 256>>>((const unsigned*)p_ei, (const unsigned*)p_batch);
    k_hist<<<EBLK2, 256>>>(p_ei);
    k_scan_bounds<<<NBLK, 256>>>(p_batch);
    k_gemm1_scatter<<<GBLK + SCB, 128>>>(x, W1r, W1l, b1, p_ei);
    k_flayer<<<FBLK, 256>>>(0, W2r, W2l, b2);     // a -> b (layer 1 act + layer 2 linear)
    k_flayer<<<FBLK, 256>>>(1, W3r, W3l, b3);     // b -> a (layer 2 act + layer 3 linear)
    k_flayer3_pool<<<FBLK, 256>>>(p_batch);       // layer 3 act + pool
    k_head<<<1, 64>>>(Wlin, blin, out);
}